// round 3
// baseline (speedup 1.0000x reference)
#include <cuda_runtime.h>
#include <math.h>

// Problem constants
#define B_  64
#define T_  512
#define H_  1024
#define I_  1024
#define M_TOK (B_ * T_)          // 32768 rows for the input projection

#define GRID_BLOCKS 128          // persistent kernel grid (must all be co-resident)
#define KSPLIT 16                // K chunks of 64
#define KCHUNK 64
#define NTILE  128               // cols per block tile

typedef unsigned long long u64t;

// ---------------------------------------------------------------------------
// Packed fp32x2 helpers (Blackwell: 2 fp32 MACs per instruction, fma pipe)
// ---------------------------------------------------------------------------
__device__ __forceinline__ u64t ffma2(u64t a, u64t b, u64t c)
{
    u64t d;
    asm("fma.rn.f32x2 %0, %1, %2, %3;" : "=l"(d) : "l"(a), "l"(b), "l"(c));
    return d;
}
__device__ __forceinline__ u64t fadd2(u64t a, u64t b)
{
    u64t d;
    asm("add.rn.f32x2 %0, %1, %2;" : "=l"(d) : "l"(a), "l"(b));
    return d;
}
__device__ __forceinline__ u64t splat2(float x)
{
    u64t d;
    unsigned r = __float_as_uint(x);
    asm("mov.b64 %0, {%1, %2};" : "=l"(d) : "r"(r), "r"(r));
    return d;
}
__device__ __forceinline__ float2 unpack2(u64t p)
{
    unsigned lo, hi;
    asm("mov.b64 {%0, %1}, %2;" : "=r"(lo), "=r"(hi) : "l"(p));
    return make_float2(__uint_as_float(lo), __uint_as_float(hi));
}

// ---------------------------------------------------------------------------
// Scratch (no cudaMalloc allowed -> __device__ globals)
// ---------------------------------------------------------------------------
__device__ float g_xw[M_TOK * H_];              // input-projection result
__device__ float g_y0[M_TOK * H_];              // layer-0 output sequence
__device__ float g_h[B_ * H_];                  // hidden state
__device__ float g_partial[KSPLIT * B_ * H_];   // split-K partials (4 MB)

// grid barrier state
__device__ unsigned g_count = 0;
__device__ volatile unsigned g_gen = 0;

__device__ __forceinline__ void grid_barrier()
{
    __syncthreads();
    if (threadIdx.x == 0) {
        unsigned gen = g_gen;
        __threadfence();                       // make prior stores visible
        unsigned a = atomicAdd(&g_count, 1);
        if (a == GRID_BLOCKS - 1) {
            atomicExch(&g_count, 0);
            __threadfence();
            g_gen = gen + 1;
        } else {
            while (g_gen == gen) { __nanosleep(64); }
        }
    }
    __syncthreads();
}

// ---------------------------------------------------------------------------
// Input-projection GEMM: C[m][n] = sum_k A[m][k] * W[n][k] + b1[n] + b2[n]
// 128x128 tile, BK=16, 256 threads, 8x8 per thread (packed fp32x2 over n).
// Register-prefetch software pipeline over K tiles.
// ---------------------------------------------------------------------------
__global__ __launch_bounds__(256) void gemm_bias_kernel(
    const float* __restrict__ A,
    const float* __restrict__ W,
    const float* __restrict__ b1,
    const float* __restrict__ b2,
    float* __restrict__ C,
    int M, int N, int K)
{
    __shared__ float As[16][128];
    __shared__ float Ws[16][128];

    const int m0 = blockIdx.y * 128;
    const int n0 = blockIdx.x * 128;
    const int tid = threadIdx.x;
    const int ty = tid >> 4;
    const int tx = tid & 15;

    const float* Ap = A + (size_t)m0 * K;
    const float* Wp = W + (size_t)n0 * K;

    // prefetch register staging: 2 float4 of A, 2 of W per thread
    const int f0  = tid;            // 0..255
    const int f1  = tid + 256;      // 256..511
    const int r0  = f0 >> 2, kq0 = (f0 & 3) * 4;
    const int r1  = f1 >> 2, kq1 = (f1 & 3) * 4;

    float4 pa0, pa1, pw0, pw1;
    {
        pa0 = *(const float4*)(Ap + (size_t)r0 * K + kq0);
        pa1 = *(const float4*)(Ap + (size_t)r1 * K + kq1);
        pw0 = *(const float4*)(Wp + (size_t)r0 * K + kq0);
        pw1 = *(const float4*)(Wp + (size_t)r1 * K + kq1);
    }

    u64t acc2[8][4];
#pragma unroll
    for (int i = 0; i < 8; i++)
#pragma unroll
        for (int j = 0; j < 4; j++) acc2[i][j] = 0ull;

    for (int k0 = 0; k0 < K; k0 += 16) {
        // commit prefetched tile to smem
        As[kq0 + 0][r0] = pa0.x; As[kq0 + 1][r0] = pa0.y;
        As[kq0 + 2][r0] = pa0.z; As[kq0 + 3][r0] = pa0.w;
        As[kq1 + 0][r1] = pa1.x; As[kq1 + 1][r1] = pa1.y;
        As[kq1 + 2][r1] = pa1.z; As[kq1 + 3][r1] = pa1.w;
        Ws[kq0 + 0][r0] = pw0.x; Ws[kq0 + 1][r0] = pw0.y;
        Ws[kq0 + 2][r0] = pw0.z; Ws[kq0 + 3][r0] = pw0.w;
        Ws[kq1 + 0][r1] = pw1.x; Ws[kq1 + 1][r1] = pw1.y;
        Ws[kq1 + 2][r1] = pw1.z; Ws[kq1 + 3][r1] = pw1.w;
        __syncthreads();

        // issue next tile's global loads (awaited next iteration)
        if (k0 + 16 < K) {
            int kn = k0 + 16;
            pa0 = *(const float4*)(Ap + (size_t)r0 * K + kn + kq0);
            pa1 = *(const float4*)(Ap + (size_t)r1 * K + kn + kq1);
            pw0 = *(const float4*)(Wp + (size_t)r0 * K + kn + kq0);
            pw1 = *(const float4*)(Wp + (size_t)r1 * K + kn + kq1);
        }

#pragma unroll
        for (int kk = 0; kk < 16; kk++) {
            float a[8];
            *(float4*)(a)     = *(const float4*)&As[kk][ty * 8];
            *(float4*)(a + 4) = *(const float4*)&As[kk][ty * 8 + 4];
            ulonglong2 wA = *(const ulonglong2*)&Ws[kk][tx * 8];
            ulonglong2 wB = *(const ulonglong2*)&Ws[kk][tx * 8 + 4];
            u64t w2[4] = { wA.x, wA.y, wB.x, wB.y };
#pragma unroll
            for (int i = 0; i < 8; i++) {
                u64t ap = splat2(a[i]);
#pragma unroll
                for (int j = 0; j < 4; j++)
                    acc2[i][j] = ffma2(ap, w2[j], acc2[i][j]);
            }
        }
        __syncthreads();
    }

    // epilogue with fused bias (packed)
    u64t bv2[4];
#pragma unroll
    for (int j = 0; j < 4; j++) {
        int n = n0 + tx * 8 + j * 2;
        float blo = b1[n] + b2[n];
        float bhi = b1[n + 1] + b2[n + 1];
        unsigned lo = __float_as_uint(blo), hi = __float_as_uint(bhi);
        u64t p;
        asm("mov.b64 %0, {%1, %2};" : "=l"(p) : "r"(lo), "r"(hi));
        bv2[j] = p;
    }
#pragma unroll
    for (int i = 0; i < 8; i++) {
        int m = m0 + ty * 8 + i;
        float* cp = C + (size_t)m * N + n0 + tx * 8;
        ulonglong2 v0, v1;
        v0.x = fadd2(acc2[i][0], bv2[0]);
        v0.y = fadd2(acc2[i][1], bv2[1]);
        v1.x = fadd2(acc2[i][2], bv2[2]);
        v1.y = fadd2(acc2[i][3], bv2[3]);
        *(ulonglong2*)(cp)     = v0;
        *(ulonglong2*)(cp + 4) = v1;
    }
}

// ---------------------------------------------------------------------------
// Persistent recurrence kernel (one launch per layer).
// Grid: 128 blocks = 8 N-tiles (128 cols) x 16 K-chunks (64 k). 256 threads.
// ---------------------------------------------------------------------------
__global__ __launch_bounds__(256) void rnn_layer_persistent(
    const float* __restrict__ Whh,    // [H, H]
    const float* __restrict__ xw,     // [B, T, H]
    float* __restrict__ y,            // [B, T, H]
    float* __restrict__ hlast)        // [B, H]
{
    __shared__ float Ws[KCHUNK][NTILE];   // 32 KB, W[c0+c][k0+k] -> Ws[k][c]
    __shared__ float Hs[KCHUNK][B_];      // 16 KB, h[b][k0+k]   -> Hs[k][b]

    const int tid = threadIdx.x;
    const int nt  = blockIdx.x >> 4;      // 0..7   N tile
    const int ks  = blockIdx.x & 15;      // 0..15  K chunk
    const int c0  = nt * NTILE;
    const int k0  = ks * KCHUNK;

    float* h       = g_h;
    float* partial = g_partial;

    // ---- load W chunk into smem once (persists across all steps) ----
    {
        int c   = tid & 127;
        int kq0 = tid >> 7;               // 0..1
#pragma unroll
        for (int i = 0; i < 8; i++) {
            int kq = kq0 + 2 * i;         // 0..15
            float4 v = *(const float4*)(Whh + (size_t)(c0 + c) * H_ + k0 + kq * 4);
            Ws[kq * 4 + 0][c] = v.x;
            Ws[kq * 4 + 1][c] = v.y;
            Ws[kq * 4 + 2][c] = v.z;
            Ws[kq * 4 + 3][c] = v.w;
        }
    }

    // ---- zero h cooperatively ----
    {
        int g = blockIdx.x * 512 + tid * 2;
        *(float2*)(h + g) = make_float2(0.0f, 0.0f);
    }
    grid_barrier();

    const int tx = tid & 15;              // col group: 8 cols
    const int ty = tid >> 4;              // row group: 4 rows

    for (int t = 0; t < T_; t++) {
        // ---------- phase A: partial[ks][b][c] = sum_k h[b][k]*W[c][k] ----------
        {
            int b   = tid & 63;
            int q0  = tid >> 6;           // 0..3
#pragma unroll
            for (int i = 0; i < 4; i++) {
                int q = q0 + 4 * i;       // 0..15
                float4 v = __ldcg((const float4*)(h + (size_t)b * H_ + k0 + q * 4));
                Hs[q * 4 + 0][b] = v.x;
                Hs[q * 4 + 1][b] = v.y;
                Hs[q * 4 + 2][b] = v.z;
                Hs[q * 4 + 3][b] = v.w;
            }
        }
        __syncthreads();

        u64t acc2[4][4];
#pragma unroll
        for (int i = 0; i < 4; i++)
#pragma unroll
            for (int j = 0; j < 4; j++) acc2[i][j] = 0ull;

#pragma unroll 4
        for (int kk = 0; kk < KCHUNK; kk++) {
            float a[4];
            *(float4*)(a) = *(const float4*)&Hs[kk][ty * 4];
            ulonglong2 wA = *(const ulonglong2*)&Ws[kk][tx * 8];
            ulonglong2 wB = *(const ulonglong2*)&Ws[kk][tx * 8 + 4];
            u64t w2[4] = { wA.x, wA.y, wB.x, wB.y };
#pragma unroll
            for (int i = 0; i < 4; i++) {
                u64t ap = splat2(a[i]);
#pragma unroll
                for (int j = 0; j < 4; j++)
                    acc2[i][j] = ffma2(ap, w2[j], acc2[i][j]);
            }
        }

        // write partial tile
#pragma unroll
        for (int i = 0; i < 4; i++) {
            int m = ty * 4 + i;
            float* pp = partial + (size_t)ks * (B_ * H_) + (size_t)m * H_ + c0 + tx * 8;
            ulonglong2 v0, v1;
            v0.x = acc2[i][0]; v0.y = acc2[i][1];
            v1.x = acc2[i][2]; v1.y = acc2[i][3];
            *(ulonglong2*)(pp)     = v0;
            *(ulonglong2*)(pp + 4) = v1;
        }

        grid_barrier();

        // ---------- phase B: reduce + tanh -> h, y ----------
        {
            int idx0 = (blockIdx.x * 256 + tid) * 2;      // 2 outputs/thread
            u64t s2 = 0ull;
#pragma unroll
            for (int k = 0; k < KSPLIT; k++) {
                u64t p = __ldcg((const u64t*)(partial + (size_t)k * (B_ * H_) + idx0));
                s2 = fadd2(s2, p);
            }
            int b = idx0 >> 10;
            int c = idx0 & 1023;
            const float* xp = xw + ((size_t)b * T_ + t) * H_ + c;
            s2 = fadd2(s2, *(const u64t*)xp);
            float2 sv = unpack2(s2);
            float2 r = make_float2(tanhf(sv.x), tanhf(sv.y));
            *(float2*)(h + idx0) = r;
            *(float2*)(y + ((size_t)b * T_ + t) * H_ + c) = r;
            if (t == T_ - 1)
                *(float2*)(hlast + idx0) = r;
        }

        grid_barrier();
    }
}

// ---------------------------------------------------------------------------
// Launcher: 4 graph nodes total.
// ---------------------------------------------------------------------------
extern "C" void kernel_launch(void* const* d_in, const int* in_sizes, int n_in,
                              void* d_out, int out_size)
{
    const float* X     = (const float*)d_in[0];
    const float* W_ih0 = (const float*)d_in[1];
    const float* b_ih0 = (const float*)d_in[2];
    const float* W_hh0 = (const float*)d_in[3];
    const float* b_hh0 = (const float*)d_in[4];
    const float* W_ih1 = (const float*)d_in[5];
    const float* b_ih1 = (const float*)d_in[6];
    const float* W_hh1 = (const float*)d_in[7];
    const float* b_hh1 = (const float*)d_in[8];

    float* out    = (float*)d_out;
    float* y_out  = out;                       // [B, T, H]
    float* h_last = out + (size_t)M_TOK * H_;  // [2, B, H]

    float* xw = nullptr;
    float* y0 = nullptr;
    cudaGetSymbolAddress((void**)&xw, g_xw);
    cudaGetSymbolAddress((void**)&y0, g_y0);

    dim3 ggrid(H_ / 128, M_TOK / 128);   // (8, 256)

    // ---------------- layer 0 ----------------
    gemm_bias_kernel<<<ggrid, 256>>>(X, W_ih0, b_ih0, b_hh0, xw, M_TOK, H_, I_);
    rnn_layer_persistent<<<GRID_BLOCKS, 256>>>(W_hh0, xw, y0, h_last);

    // ---------------- layer 1 ----------------
    gemm_bias_kernel<<<ggrid, 256>>>(y0, W_ih1, b_ih1, b_hh1, xw, M_TOK, H_, H_);
    rnn_layer_persistent<<<GRID_BLOCKS, 256>>>(W_hh1, xw, y_out, h_last + B_ * H_);
}